// round 10
// baseline (speedup 1.0000x reference)
#include <cuda_runtime.h>
#include <cstdint>

// EdgeFeaturizer: per-row 12-NN (lexicographic (dist, idx), radius-masked) +
// Gaussian RBF expansion over 50 centers.
//
// Output layout (float32, flattened tuple in reference return order):
//   [0          .. N*K*2)          edge_index  (src, nbr) pairs, row-major
//   [N*K*2      .. N*K*2+N*K*50)   edge_features row-major [N*K, 50]

#define N_ATOMS    8192
#define KNN        12
#define NBINS      50
#define TPB        512
#define F4PT       (N_ATOMS / 4 / TPB)   // 4 float4 per thread
#define CAND_MAX   256
#define THRESH     0.006f     // lambda = 49.1 expected candidates/row;
                              // P(C < 12) ~ 4e-11 -> exact fallback below
#define MAXRAD     8.0f

__device__ __forceinline__ unsigned long long warp_min_u64(unsigned long long v) {
#pragma unroll
    for (int off = 16; off; off >>= 1) {
        unsigned long long o = __shfl_xor_sync(0xffffffffu, v, off);
        v = (o < v) ? o : v;
    }
    return v;
}

__device__ __forceinline__ void insert12(unsigned long long (&best)[KNN],
                                         unsigned long long key) {
    if (key < best[KNN - 1]) {
#pragma unroll
        for (int s = 0; s < KNN; ++s) {
            if (key < best[s]) {
                unsigned long long t = best[s];
                best[s] = key;
                key = t;
            }
        }
    }
}

__global__ __launch_bounds__(TPB, 3) void edge_featurizer_kernel(
    const float* __restrict__ dm, float* __restrict__ out) {
    __shared__ unsigned long long cand[CAND_MAX];
    __shared__ unsigned long long fin[KNN];
    __shared__ __align__(16) float feat[KNN * NBINS];  // 600 floats
    __shared__ int cnt;

    const int row = blockIdx.x;
    const int tid = threadIdx.x;
    if (tid == 0) cnt = 0;
    __syncthreads();

    // ---- Pass 1: streaming scan. Front-batch 4 LDG.128 per thread, then
    //      group-min pre-filter: only descend to per-element checks when the
    //      float4's min is below threshold. ----
    const float4* rp = (const float4*)(dm + (size_t)row * N_ATOMS);
    float4 v[F4PT];
#pragma unroll
    for (int i = 0; i < F4PT; ++i)
        v[i] = __ldcs(rp + tid + i * TPB);

#pragma unroll
    for (int i = 0; i < F4PT; ++i) {
        float a0 = v[i].x, a1 = v[i].y, a2 = v[i].z, a3 = v[i].w;
        float m = fminf(fminf(a0, a1), fminf(a2, a3));
        if (m < THRESH) {
            int base = (tid + i * TPB) * 4;
#pragma unroll
            for (int c = 0; c < 4; ++c) {
                float x = (c == 0) ? a0 : (c == 1) ? a1 : (c == 2) ? a2 : a3;
                if (x < THRESH) {
                    int p = atomicAdd(&cnt, 1);
                    if (p < CAND_MAX)
                        cand[p] =
                            ((unsigned long long)__float_as_uint(x) << 32) |
                            (unsigned)(base + c);
                }
            }
        }
    }
    __syncthreads();

    const int C = cnt;
    const bool fast = (C >= KNN) && (C <= CAND_MAX);

    if (fast) {
        // ---- Rank selection: keys are unique (index embedded), so ranks are
        //      a permutation. Thread t owns cand[t]; rank = #smaller keys.
        //      Flat smem-broadcast loop, fully parallel. ----
        if (tid < C) {
            const unsigned long long my = cand[tid];
            int rankv = 0;
            for (int i = 0; i < C; ++i)
                rankv += (cand[i] < my);
            if (rankv < KNN) fin[rankv] = my;
        }
    } else if (tid < 32) {
        // Exact fallback: full-row scan by warp 0 (radius-masked).
        // Statistically unreachable for this input; kept for correctness.
        unsigned long long best[KNN];
#pragma unroll
        for (int s = 0; s < KNN; ++s) best[s] = ~0ull;
        const float* r = dm + (size_t)row * N_ATOMS;
        for (int j = tid; j < N_ATOMS; j += 32) {
            float x = r[j];
            if (x <= MAXRAD) {
                unsigned long long key =
                    ((unsigned long long)__float_as_uint(x) << 32) |
                    (unsigned)j;
                insert12(best, key);
            }
        }
        int p = 0;
#pragma unroll
        for (int it = 0; it < KNN; ++it) {
            unsigned long long my = (p < KNN) ? best[p] : ~0ull;
            unsigned long long m = warp_min_u64(my);
            if (my == m) p++;
            if (tid == 0) fin[it] = m;
        }
    }
    __syncthreads();

    // ---- edge_index: (src=row, nbr=idx_j), row-major over [N*K, 2] ----
    if (tid < 2 * KNN) {
        int j = tid >> 1;
        float vv = (tid & 1) ? (float)(unsigned)(fin[j] & 0xffffffffu)
                             : (float)row;
        out[(size_t)row * (2 * KNN) + tid] = vv;
    }

    // ---- edge_features via Gaussian recurrence ----
    // f(x) = exp(-12.5 (d-x)^2), x = c*delta.
    //   f(x+delta) = f(x) * g(x),  g(x+delta) = g(x) * kconst
    // 24 threads: thread t handles edge j = t>>1, bins [h*25, h*25+25).
    if (tid < 2 * KNN) {
        const int j = tid >> 1;
        const int h = tid & 1;
        const float delta = 1.0f / 49.0f;
        const float d = __uint_as_float((unsigned)(fin[j] >> 32));
        const float x0 = (float)(h * 25) * delta;
        const float z0 = (d - x0) * 5.0f;
        float f = __expf(-0.5f * z0 * z0);
        float g = __expf(-12.5f * delta * (delta - 2.0f * (d - x0)));
        const float kconst = __expf(-25.0f * delta * delta);
        float* fr = feat + j * NBINS + h * 25;
#pragma unroll
        for (int i = 0; i < 25; ++i) {
            fr[i] = f;
            f *= g;
            g *= kconst;
        }
    }
    __syncthreads();

    // Coalesced float4 store of the 600-float feature block.
    const size_t featBase = (size_t)N_ATOMS * (2 * KNN);
    float4* o4 = (float4*)(out + featBase) + (size_t)row * (KNN * NBINS / 4);
    const float4* s4 = (const float4*)feat;
    if (tid < KNN * NBINS / 4)  // 150 float4
        o4[tid] = s4[tid];
}

extern "C" void kernel_launch(void* const* d_in, const int* in_sizes, int n_in,
                              void* d_out, int out_size) {
    const float* dm = (const float*)d_in[0];
    float* out = (float*)d_out;
    edge_featurizer_kernel<<<N_ATOMS, TPB>>>(dm, out);
}

// round 14
// speedup vs baseline: 1.2206x; 1.2206x over previous
#include <cuda_runtime.h>
#include <cstdint>

// EdgeFeaturizer: per-row 12-NN (lexicographic (dist, idx), radius-masked) +
// Gaussian RBF expansion over 50 centers.
//
// Output layout (float32, flattened tuple in reference return order):
//   [0          .. N*K*2)          edge_index  (src, nbr) pairs, row-major
//   [N*K*2      .. N*K*2+N*K*50)   edge_features row-major [N*K, 50]

#define N_ATOMS    8192
#define KNN        12
#define NBINS      50
#define TPB        256
#define F4PT       (N_ATOMS / 4 / TPB)   // 8 float4 per thread
#define CAND_MAX   256
#define THRESH     0.006f     // lambda = 49.1 expected candidates/row;
                              // P(C < 12) ~ 4e-11 -> exact fallback below
#define MAXRAD     8.0f

__device__ __forceinline__ unsigned long long warp_min_u64(unsigned long long v) {
#pragma unroll
    for (int off = 16; off; off >>= 1) {
        unsigned long long o = __shfl_xor_sync(0xffffffffu, v, off);
        v = (o < v) ? o : v;
    }
    return v;
}

__device__ __forceinline__ void insert12(unsigned long long (&best)[KNN],
                                         unsigned long long key) {
    if (key < best[KNN - 1]) {
#pragma unroll
        for (int s = 0; s < KNN; ++s) {
            if (key < best[s]) {
                unsigned long long t = best[s];
                best[s] = key;
                key = t;
            }
        }
    }
}

__global__ __launch_bounds__(TPB, 5) void edge_featurizer_kernel(
    const float* __restrict__ dm, float* __restrict__ out) {
    __shared__ unsigned long long cand[CAND_MAX];
    __shared__ unsigned long long fin[KNN];
    __shared__ __align__(16) float feat[KNN * NBINS];  // 600 floats
    __shared__ int cnt;

    const int row = blockIdx.x;
    const int tid = threadIdx.x;
    if (tid == 0) cnt = 0;
    __syncthreads();

    // ---- Pass 1: streaming scan. Front-batch all 8 LDG.128 (MLP=8), then
    //      group-min pre-filter: descend to per-element checks only when the
    //      float4's min is below threshold (~2.4% of groups). ----
    const float4* rp = (const float4*)(dm + (size_t)row * N_ATOMS);
    float4 v[F4PT];
#pragma unroll
    for (int i = 0; i < F4PT; ++i)
        v[i] = __ldcs(rp + tid + i * TPB);

#pragma unroll
    for (int i = 0; i < F4PT; ++i) {
        float a0 = v[i].x, a1 = v[i].y, a2 = v[i].z, a3 = v[i].w;
        float m = fminf(fminf(a0, a1), fminf(a2, a3));
        if (m < THRESH) {
            int base = (tid + i * TPB) * 4;
#pragma unroll
            for (int c = 0; c < 4; ++c) {
                float x = (c == 0) ? a0 : (c == 1) ? a1 : (c == 2) ? a2 : a3;
                if (x < THRESH) {
                    int p = atomicAdd(&cnt, 1);
                    if (p < CAND_MAX)
                        cand[p] =
                            ((unsigned long long)__float_as_uint(x) << 32) |
                            (unsigned)(base + c);
                }
            }
        }
    }
    __syncthreads();

    const int C = cnt;
    const bool fast = (C >= KNN) && (C <= CAND_MAX);

    if (fast) {
        // ---- Rank selection: keys are unique (index embedded), so ranks are
        //      a permutation. Thread t owns cand[t]; rank = #smaller keys.
        //      Flat smem-broadcast loop, fully parallel. ----
        if (tid < C) {
            const unsigned long long my = cand[tid];
            int rankv = 0;
            for (int i = 0; i < C; ++i)
                rankv += (cand[i] < my);
            if (rankv < KNN) fin[rankv] = my;
        }
    } else if (tid < 32) {
        // Exact fallback: full-row scan by warp 0 (radius-masked).
        // Statistically unreachable for this input; kept for correctness.
        unsigned long long best[KNN];
#pragma unroll
        for (int s = 0; s < KNN; ++s) best[s] = ~0ull;
        const float* r = dm + (size_t)row * N_ATOMS;
        for (int j = tid; j < N_ATOMS; j += 32) {
            float x = r[j];
            if (x <= MAXRAD) {
                unsigned long long key =
                    ((unsigned long long)__float_as_uint(x) << 32) |
                    (unsigned)j;
                insert12(best, key);
            }
        }
        int p = 0;
#pragma unroll
        for (int it = 0; it < KNN; ++it) {
            unsigned long long my = (p < KNN) ? best[p] : ~0ull;
            unsigned long long m = warp_min_u64(my);
            if (my == m) p++;
            if (tid == 0) fin[it] = m;
        }
    }
    __syncthreads();

    // ---- edge_index: (src=row, nbr=idx_j), row-major over [N*K, 2] ----
    if (tid < 2 * KNN) {
        int j = tid >> 1;
        float vv = (tid & 1) ? (float)(unsigned)(fin[j] & 0xffffffffu)
                             : (float)row;
        out[(size_t)row * (2 * KNN) + tid] = vv;
    }

    // ---- edge_features via Gaussian recurrence ----
    // f(x) = exp(-12.5 (d-x)^2), x = c*delta.
    //   f(x+delta) = f(x) * g(x),  g(x+delta) = g(x) * kconst
    // 24 threads: thread t handles edge j = t>>1, bins [h*25, h*25+25).
    if (tid < 2 * KNN) {
        const int j = tid >> 1;
        const int h = tid & 1;
        const float delta = 1.0f / 49.0f;
        const float d = __uint_as_float((unsigned)(fin[j] >> 32));
        const float x0 = (float)(h * 25) * delta;
        const float z0 = (d - x0) * 5.0f;
        float f = __expf(-0.5f * z0 * z0);
        float g = __expf(-12.5f * delta * (delta - 2.0f * (d - x0)));
        const float kconst = __expf(-25.0f * delta * delta);
        float* fr = feat + j * NBINS + h * 25;
#pragma unroll
        for (int i = 0; i < 25; ++i) {
            fr[i] = f;
            f *= g;
            g *= kconst;
        }
    }
    __syncthreads();

    // Coalesced float4 store of the 600-float feature block.
    const size_t featBase = (size_t)N_ATOMS * (2 * KNN);
    float4* o4 = (float4*)(out + featBase) + (size_t)row * (KNN * NBINS / 4);
    const float4* s4 = (const float4*)feat;
    if (tid < KNN * NBINS / 4)  // 150 float4
        o4[tid] = s4[tid];
}

extern "C" void kernel_launch(void* const* d_in, const int* in_sizes, int n_in,
                              void* d_out, int out_size) {
    const float* dm = (const float*)d_in[0];
    float* out = (float*)d_out;
    edge_featurizer_kernel<<<N_ATOMS, TPB>>>(dm, out);
}